// round 3
// baseline (speedup 1.0000x reference)
#include <cuda_runtime.h>
#include <cuda_bf16.h>
#include <math.h>

// FusedCirculantBlock: SignFlip -> per-block rFFT(512) -> 8x8 spectral mix -> irFFT -> bias -> erf-GELU
// B=2, S=4096, F_IN=F_OUT=4096, P=512, Q_IN=Q_OUT=8.
//
// Strategy: fused fp32 FFT path. One CTA handles 2 tokens (amortizes spectral
// weight reads). Radix-8 Stockham FFT-512 in shared memory (3 stages).
// Real-pair packing: blocks (2j, 2j+1) share one complex FFT both directions.
// Wf precomputed once per launch (in-graph) as DFT(w)/1024 — folds the 1/2
// rfft-unpack factor and the 1/512 inverse-FFT normalization.

#define P512 512
#define QB 8            // blocks per side
#define NF 257          // rfft bins
#define FFTPAD 576      // 512 + 512/8 padding slots
#define TPB 256

__device__ float2 g_tw[512];          // exp(-2*pi*i*k/512)
__device__ float  g_sf[4096];         // 1 - 2*sign_bits
__device__ float2 g_Wf[64 * NF];      // [o][i][f], scaled by 1/1024

static __device__ __forceinline__ int PAD(int i) { return i + (i >> 3); }

static __device__ __forceinline__ float2 cadd(float2 a, float2 b) { return make_float2(a.x + b.x, a.y + b.y); }
static __device__ __forceinline__ float2 csub(float2 a, float2 b) { return make_float2(a.x - b.x, a.y - b.y); }
static __device__ __forceinline__ float2 cmul(float2 a, float2 w) {
    return make_float2(a.x * w.x - a.y * w.y, a.x * w.y + a.y * w.x);
}
static __device__ __forceinline__ float2 cfma(float2 x, float2 w, float2 acc) {
    acc.x = fmaf(x.x, w.x, fmaf(-x.y, w.y, acc.x));
    acc.y = fmaf(x.x, w.y, fmaf(x.y, w.x, acc.y));
    return acc;
}

static __device__ __forceinline__ float gelu_erf(float v) {
    return 0.5f * v * (1.0f + erff(v * 0.70710678118654752f));
}

// 8-point DFT: b_u = sum_r a_r * w8^{u*r}; w8 = exp(-2*pi*i/8) fwd (INV=0), conj for INV=1
template <int INV>
static __device__ __forceinline__ void dft8(float2 a[8]) {
    const float C = 0.70710678118654752f;
    float2 s0 = cadd(a[0], a[4]), s1 = csub(a[0], a[4]);
    float2 s2 = cadd(a[2], a[6]), s3 = csub(a[2], a[6]);
    float2 u0 = cadd(a[1], a[5]), u1 = csub(a[1], a[5]);
    float2 u2 = cadd(a[3], a[7]), u3 = csub(a[3], a[7]);
    float2 E0 = cadd(s0, s2), E2 = csub(s0, s2);
    float2 O0 = cadd(u0, u2), O2 = csub(u0, u2);
    float2 E1, E3, O1, O3, t1, t2, t3;
    if (!INV) {
        E1 = make_float2(s1.x + s3.y, s1.y - s3.x);   // s1 - i*s3
        E3 = make_float2(s1.x - s3.y, s1.y + s3.x);   // s1 + i*s3
        O1 = make_float2(u1.x + u3.y, u1.y - u3.x);
        O3 = make_float2(u1.x - u3.y, u1.y + u3.x);
        t1 = make_float2(C * (O1.x + O1.y), C * (O1.y - O1.x));   // c(1-i)*O1
        t2 = make_float2(O2.y, -O2.x);                            // -i*O2
        t3 = make_float2(C * (O3.y - O3.x), -C * (O3.x + O3.y));  // -c(1+i)*O3
    } else {
        E1 = make_float2(s1.x - s3.y, s1.y + s3.x);   // s1 + i*s3
        E3 = make_float2(s1.x + s3.y, s1.y - s3.x);
        O1 = make_float2(u1.x - u3.y, u1.y + u3.x);
        O3 = make_float2(u1.x + u3.y, u1.y - u3.x);
        t1 = make_float2(C * (O1.x - O1.y), C * (O1.x + O1.y));   // c(1+i)*O1
        t2 = make_float2(-O2.y, O2.x);                            // +i*O2
        t3 = make_float2(-C * (O3.x + O3.y), C * (O3.x - O3.y));  // c(-1+i)*O3
    }
    a[0] = cadd(E0, O0); a[4] = csub(E0, O0);
    a[1] = cadd(E1, t1); a[5] = csub(E1, t1);
    a[2] = cadd(E2, t2); a[6] = csub(E2, t2);
    a[3] = cadd(E3, t3); a[7] = csub(E3, t3);
}

// Radix-8 Stockham FFT-512. Input in bufA; result lands in bufB (A->B->A->B).
// All 256 threads of the block must call (internal __syncthreads). t in [0,64).
template <int INV>
static __device__ __forceinline__ void fft512(float2* bufA, float2* bufB,
                                              const float2* tw, int t) {
    float2 a[8];
    {   // stage 0: n=512, s=1, m=64
        int p = t;
        #pragma unroll
        for (int r = 0; r < 8; r++) a[r] = bufA[PAD(p + 64 * r)];
        dft8<INV>(a);
        bufB[PAD(8 * p)] = a[0];
        #pragma unroll
        for (int u = 1; u < 8; u++) {
            float2 w = tw[(u * p) & 511];
            if (INV) w.y = -w.y;
            bufB[PAD(8 * p + u)] = cmul(a[u], w);
        }
    }
    __syncthreads();
    {   // stage 1: n=64, s=8, m=8
        int q = t & 7, p = t >> 3;
        #pragma unroll
        for (int r = 0; r < 8; r++) a[r] = bufB[PAD(q + 8 * p + 64 * r)];
        dft8<INV>(a);
        bufA[PAD(q + 64 * p)] = a[0];
        #pragma unroll
        for (int u = 1; u < 8; u++) {
            float2 w = tw[(8 * u * p) & 511];
            if (INV) w.y = -w.y;
            bufA[PAD(q + 64 * p + 8 * u)] = cmul(a[u], w);
        }
    }
    __syncthreads();
    {   // stage 2: n=8, s=64, m=1
        int q = t;
        #pragma unroll
        for (int r = 0; r < 8; r++) a[r] = bufA[PAD(q + 64 * r)];
        dft8<INV>(a);
        #pragma unroll
        for (int u = 0; u < 8; u++) bufB[PAD(q + 64 * u)] = a[u];
    }
    __syncthreads();
}

// ---------------- precompute kernels (run inside the graph, cheap) ----------

__global__ void precompute_tw_sf(const int* __restrict__ sign_bits) {
    int k = threadIdx.x;  // 512 threads
    float s, c;
    sincospif((float)k / 256.0f, &s, &c);   // angle = 2*pi*k/512
    g_tw[k] = make_float2(c, -s);
    for (int e = k; e < 4096; e += 512)
        g_sf[e] = 1.0f - 2.0f * (float)sign_bits[e];
}

__global__ void precompute_wf(const float* __restrict__ w) {
    __shared__ float2 stw[512];
    __shared__ float  sw[512];
    int blk = blockIdx.x;  // o*8+i
    for (int k = threadIdx.x; k < 512; k += blockDim.x) {
        stw[k] = g_tw[k];
        sw[k] = w[blk * 512 + k];
    }
    __syncthreads();
    for (int f = threadIdx.x; f <= 256; f += blockDim.x) {
        float re = 0.0f, im = 0.0f;
        for (int n = 0; n < 512; n++) {
            float2 t = stw[(f * n) & 511];
            float wv = sw[n];
            re = fmaf(wv, t.x, re);
            im = fmaf(wv, t.y, im);
        }
        // fold 1/2 (rfft pack skips /2 -> X stored as 2X) and 1/512 (inverse scale)
        g_Wf[blk * NF + f] = make_float2(re * (1.0f / 1024.0f), im * (1.0f / 1024.0f));
    }
}

// ---------------- main fused kernel ----------------------------------------
// grid = BS/2 blocks, 256 threads. SMEM: tw[512] | PQ[2][4][576] | Xf[2][8][257]

__global__ void __launch_bounds__(TPB, 3)
fused_main(const float* __restrict__ x, const float* __restrict__ bias,
           float* __restrict__ out) {
    extern __shared__ float2 sm[];
    float2* s_tw = sm;                       // 512
    float2* s_PQ = sm + 512;                 // 2 * 4 * 576 = 4608
    float2* s_Xf = sm + 512 + 2 * 4 * FFTPAD;  // 2 * 8 * 257 = 4112

    const int tid = threadIdx.x;
    const int j   = tid >> 6;        // pair id 0..3 (x-block pair / o-pair / fft lane group)
    const int t6  = tid & 63;

    for (int k = tid; k < 512; k += TPB) s_tw[k] = g_tw[k];

    const long long tok0 = (long long)blockIdx.x * 2;
    const float* x0 = x + tok0 * 4096;
    float*       o0 = out + tok0 * 4096;

    float2* bufA = s_PQ;                 // forward ping
    float2* bufB = s_PQ + 4 * FFTPAD;    // forward pong (result)

    // ---------------- forward FFTs (both tokens) ----------------
    for (int tk = 0; tk < 2; tk++) {
        __syncthreads();  // tw ready / prior unpack done / bufA free
        const float* xr = x0 + tk * 4096 + j * 1024;
        const float* sf = g_sf + j * 1024;
        float2* A = bufA + j * FFTPAD;
        #pragma unroll
        for (int k = 0; k < 8; k++) {
            int n = t6 + 64 * k;
            float re = xr[n]       * sf[n];
            float im = xr[n + 512] * sf[n + 512];
            A[PAD(n)] = make_float2(re, im);
        }
        __syncthreads();
        fft512<0>(bufA + j * FFTPAD, bufB + j * FFTPAD, s_tw, t6);
        // unpack Z -> X_{2j}, X_{2j+1} (store 2*X; the 1/2 is folded into Wf)
        float2* Z  = bufB + j * FFTPAD;
        float2* X0 = s_Xf + tk * (QB * NF) + (2 * j) * NF;
        float2* X1 = X0 + NF;
        for (int f = t6; f <= 256; f += 64) {
            float2 zf = Z[PAD(f)];
            float2 zm = Z[PAD((512 - f) & 511)];
            X0[f] = make_float2(zf.x + zm.x, zf.y - zm.y);      //   Z + conj(Zm)
            X1[f] = make_float2(zf.y + zm.y, zm.x - zf.x);      // -i(Z - conj(Zm))
        }
    }
    __syncthreads();

    // ---------------- pointwise spectral mix + Hermitian pack ---------------
    // thread (opair=j, f): Wf regs loaded once, applied to both tokens.
    {
        const int opair = j;
        for (int f = t6; f <= 256; f += 64) {
            float2 w0[8], w1[8];
            const float2* Wp0 = g_Wf + (size_t)(2 * opair) * QB * NF + f;
            const float2* Wp1 = Wp0 + QB * NF;
            #pragma unroll
            for (int i = 0; i < 8; i++) { w0[i] = Wp0[i * NF]; w1[i] = Wp1[i * NF]; }
            #pragma unroll
            for (int tk = 0; tk < 2; tk++) {
                const float2* Xp = s_Xf + tk * (QB * NF) + f;
                float2 y0 = make_float2(0.f, 0.f), y1 = make_float2(0.f, 0.f);
                #pragma unroll
                for (int i = 0; i < 8; i++) {
                    float2 xv = Xp[i * NF];
                    y0 = cfma(xv, w0[i], y0);
                    y1 = cfma(xv, w1[i], y1);
                }
                float2* Zb = s_PQ + tk * (4 * FFTPAD) + opair * FFTPAD;
                if (f == 0 || f == 256) {
                    Zb[PAD(f)] = make_float2(y0.x, y1.x);  // DC/Nyquist: real parts only
                } else {
                    Zb[PAD(f)]       = make_float2(y0.x - y1.y, y0.y + y1.x); // Y0 + i*Y1
                    Zb[PAD(512 - f)] = make_float2(y0.x + y1.y, y1.x - y0.y); // conj ext.
                }
            }
        }
    }
    __syncthreads();

    // ---------------- inverse FFTs + epilogue (per token) -------------------
    float2* S = s_Xf;  // scratch (4*576 = 2304 <= 4112), Xf dead now
    for (int tk = 0; tk < 2; tk++) {
        float2* Zb = s_PQ + tk * (4 * FFTPAD);
        fft512<1>(Zb + j * FFTPAD, S + j * FFTPAD, s_tw, t6);  // result in S
        const float* br   = bias + j * 1024;
        float*       orow = o0 + tk * 4096 + j * 1024;
        const float2* Sj  = S + j * FFTPAD;
        #pragma unroll
        for (int k = 0; k < 8; k++) {
            int n = t6 + 64 * k;
            float2 v = Sj[PAD(n)];
            orow[n]       = gelu_erf(v.x + br[n]);
            orow[n + 512] = gelu_erf(v.y + br[n + 512]);
        }
        __syncthreads();  // S free for next token
    }
}

// ---------------- launch ----------------------------------------------------

extern "C" void kernel_launch(void* const* d_in, const int* in_sizes, int n_in,
                              void* d_out, int out_size) {
    const float* x         = (const float*)d_in[0];
    const float* w         = (const float*)d_in[1];
    const float* bias      = (const float*)d_in[2];
    const int*   sign_bits = (const int*)d_in[3];
    float* out = (float*)d_out;

    const int BS = in_sizes[0] / 4096;   // 8192 tokens
    const size_t smem = (size_t)(512 + 2 * 4 * FFTPAD + 2 * QB * NF) * sizeof(float2);  // 73856 B

    cudaFuncSetAttribute(fused_main, cudaFuncAttributeMaxDynamicSharedMemorySize, (int)smem);

    precompute_tw_sf<<<1, 512>>>(sign_bits);
    precompute_wf<<<64, 256>>>(w);
    fused_main<<<BS / 2, TPB, smem>>>(x, bias, out);
}